// round 5
// baseline (speedup 1.0000x reference)
#include <cuda_runtime.h>
#include <math.h>

#define NN 50000
#define EE 800000
#define ET (EE + NN)
#define FIN 256
#define HH 64
#define CC 40
#define NEG_SLOPE 0.2f
#define NB ((NN + 255) / 256)

typedef unsigned long long u64;

// ---------------- scratch (__device__ globals; no allocation) ----------------
static __device__ int g_is64;
static __device__ int g_src[ET];
static __device__ int g_dst[ET];
static __device__ int g_cnt[NN];
static __device__ int g_roff[NN + 1];
static __device__ int g_cursor[NN];
static __device__ int g_csrc[ET];
static __device__ int g_bsum[NB];
static __device__ int g_bpre[NB];

static __device__ float g_xl1[NN * HH];
static __device__ float g_xr1[NN * HH];
static __device__ float g_ln1[NN * HH];
static __device__ float g_h[NN * HH];

static __device__ float g_xl2[NN * CC];
static __device__ float g_xr2[NN * CC];
static __device__ float g_ln2[NN * CC];

// ---------------- f32x2 packed-FMA helpers (sm_103a) ----------------
__device__ __forceinline__ void fma2(u64& acc, u64 a, u64 b) {
    asm("fma.rn.f32x2 %0, %1, %2, %0;" : "+l"(acc) : "l"(a), "l"(b));
}
__device__ __forceinline__ u64 pk(float lo, float hi) {
    u64 r;
    asm("mov.b64 %0, {%1, %2};" : "=l"(r) : "f"(lo), "f"(hi));
    return r;
}
__device__ __forceinline__ float plo(u64 v) { return __uint_as_float((unsigned)v); }
__device__ __forceinline__ float phi(u64 v) { return __uint_as_float((unsigned)(v >> 32)); }

__device__ __forceinline__ float lrelu(float v) { return fmaxf(v, NEG_SLOPE * v); }

// ---------------- edge index dtype detect ----------------
__global__ void detect_kernel(const void* edge) {
    const int* p = (const int*)edge;
    int ok64 = 1;
    for (int i = threadIdx.x * 2 + 1; i < 4096; i += 64)
        if (p[i] != 0) ok64 = 0;
    unsigned b = __ballot_sync(0xffffffffu, ok64);
    if (threadIdx.x == 0) g_is64 = (b == 0xffffffffu) ? 1 : 0;
}

__global__ void zero_cnt_kernel() {
    int i = blockIdx.x * blockDim.x + threadIdx.x;
    if (i < NN) g_cnt[i] = 0;
}

// convert edge list (+self loops), histogram dst, emit edge_index passthrough
__global__ void convert_count_kernel(const void* edge, float* __restrict__ out, int do_pass) {
    int t = blockIdx.x * blockDim.x + threadIdx.x;
    if (t >= ET) return;
    int s, d;
    if (t >= EE) {
        s = t - EE; d = t - EE;
    } else if (g_is64) {
        const long long* p = (const long long*)edge;
        s = (int)p[t]; d = (int)p[EE + t];
    } else {
        const int* p = (const int*)edge;
        s = p[t]; d = p[EE + t];
    }
    g_src[t] = s;
    g_dst[t] = d;
    atomicAdd(&g_cnt[d], 1);
    if (do_pass && t < EE) {
        out[NN * CC + t] = (float)s;
        out[NN * CC + EE + t] = (float)d;
    }
}

// ---------------- 3-stage parallel scan over g_cnt ----------------
__global__ void bsum_kernel() {
    __shared__ int ws[8];
    int i = blockIdx.x * 256 + threadIdx.x;
    int lane = threadIdx.x & 31, w = threadIdx.x >> 5;
    int v = (i < NN) ? g_cnt[i] : 0;
#pragma unroll
    for (int o = 16; o > 0; o >>= 1) v += __shfl_xor_sync(0xffffffffu, v, o);
    if (lane == 0) ws[w] = v;
    __syncthreads();
    if (threadIdx.x == 0) {
        int s = 0;
#pragma unroll
        for (int k = 0; k < 8; k++) s += ws[k];
        g_bsum[blockIdx.x] = s;
    }
}

__global__ void bscan_kernel() {  // 1 block, 256 threads; NB <= 256
    __shared__ int ws[8];
    int t = threadIdx.x;
    int lane = t & 31, w = t >> 5;
    int v = (t < NB) ? g_bsum[t] : 0;
    int x = v;
#pragma unroll
    for (int dlt = 1; dlt < 32; dlt <<= 1) {
        int y = __shfl_up_sync(0xffffffffu, x, dlt);
        if (lane >= dlt) x += y;
    }
    if (lane == 31) ws[w] = x;
    __syncthreads();
    if (w == 0 && lane < 8) {
        int s = ws[lane];
#pragma unroll
        for (int dlt = 1; dlt < 8; dlt <<= 1) {
            int y = __shfl_up_sync(0xffu, s, dlt);
            if (lane >= dlt) s += y;
        }
        ws[lane] = s;
    }
    __syncthreads();
    int prefix = (w > 0) ? ws[w - 1] : 0;
    if (t < NB) g_bpre[t] = prefix + x - v;
}

__global__ void offs_kernel() {
    __shared__ int ws[8];
    int i = blockIdx.x * 256 + threadIdx.x;
    int lane = threadIdx.x & 31, w = threadIdx.x >> 5;
    int v = (i < NN) ? g_cnt[i] : 0;
    int x = v;
#pragma unroll
    for (int dlt = 1; dlt < 32; dlt <<= 1) {
        int y = __shfl_up_sync(0xffffffffu, x, dlt);
        if (lane >= dlt) x += y;
    }
    if (lane == 31) ws[w] = x;
    __syncthreads();
    if (w == 0 && lane < 8) {
        int s = ws[lane];
#pragma unroll
        for (int dlt = 1; dlt < 8; dlt <<= 1) {
            int y = __shfl_up_sync(0xffu, s, dlt);
            if (lane >= dlt) s += y;
        }
        ws[lane] = s;
    }
    __syncthreads();
    int prefix = (w > 0) ? ws[w - 1] : 0;
    int excl = g_bpre[blockIdx.x] + prefix + x - v;
    if (i < NN) {
        g_cursor[i] = excl;
        g_roff[i + 1] = excl + v;
    }
    if (i == 0) g_roff[0] = 0;
}

__global__ void scatter_kernel() {
    int t = blockIdx.x * blockDim.x + threadIdx.x;
    if (t >= ET) return;
    int d = g_dst[t];
    int pos = atomicAdd(&g_cursor[d], 1);
    g_csrc[pos] = g_src[t];
}

// ---------------- layer1 node GEMMs: xl1/xr1/lin1 fused, f32x2 ----------------
__global__ void __launch_bounds__(128) gemm1_kernel(
    const float* __restrict__ x,
    const float* __restrict__ Wl, const float* __restrict__ bl,
    const float* __restrict__ Wr, const float* __restrict__ br,
    const float* __restrict__ Wn, const float* __restrict__ bn) {
    __shared__ float4 xs[2][16 * 64];
    const int t = threadIdx.x & 63;
    const int g = threadIdx.x >> 6;
    const int row0 = blockIdx.x * 32 + g * 16;
    const float4* x4 = (const float4*)x;
#pragma unroll
    for (int i = 0; i < 16; i++) {
        int r = row0 + i;
        float4 v = make_float4(0.f, 0.f, 0.f, 0.f);
        if (r < NN) v = x4[r * 64 + t];
        xs[g][i * 64 + t] = v;
    }
    __syncthreads();

    u64 Pl[8], Pr[8], Pn[8];
#pragma unroll
    for (int m = 0; m < 8; m++) { Pl[m] = 0ull; Pr[m] = 0ull; Pn[m] = 0ull; }

    for (int k4 = 0; k4 < 64; k4++) {
        int k = 4 * k4;
        u64 WL[4], WR[4], WN[4];
#pragma unroll
        for (int j = 0; j < 4; j++) {
            float wl = __ldg(&Wl[(k + j) * HH + t]);
            float wr = __ldg(&Wr[(k + j) * HH + t]);
            float wn = __ldg(&Wn[(k + j) * HH + t]);
            WL[j] = pk(wl, wl);
            WR[j] = pk(wr, wr);
            WN[j] = pk(wn, wn);
        }
#pragma unroll
        for (int m2 = 0; m2 < 8; m2++) {
            float4 xa = xs[g][(2 * m2) * 64 + k4];
            float4 xb = xs[g][(2 * m2 + 1) * 64 + k4];
            u64 p0 = pk(xa.x, xb.x);
            u64 p1 = pk(xa.y, xb.y);
            u64 p2 = pk(xa.z, xb.z);
            u64 p3 = pk(xa.w, xb.w);
            fma2(Pl[m2], p0, WL[0]); fma2(Pr[m2], p0, WR[0]); fma2(Pn[m2], p0, WN[0]);
            fma2(Pl[m2], p1, WL[1]); fma2(Pr[m2], p1, WR[1]); fma2(Pn[m2], p1, WN[1]);
            fma2(Pl[m2], p2, WL[2]); fma2(Pr[m2], p2, WR[2]); fma2(Pn[m2], p2, WN[2]);
            fma2(Pl[m2], p3, WL[3]); fma2(Pr[m2], p3, WR[3]); fma2(Pn[m2], p3, WN[3]);
        }
    }
    float vbl = __ldg(&bl[t]), vbr = __ldg(&br[t]), vbn = __ldg(&bn[t]);
#pragma unroll
    for (int m2 = 0; m2 < 8; m2++) {
        int ra = row0 + 2 * m2, rb = ra + 1;
        if (ra < NN) {
            g_xl1[ra * HH + t] = plo(Pl[m2]) + vbl;
            g_xr1[ra * HH + t] = plo(Pr[m2]) + vbr;
            g_ln1[ra * HH + t] = plo(Pn[m2]) + vbn;
        }
        if (rb < NN) {
            g_xl1[rb * HH + t] = phi(Pl[m2]) + vbl;
            g_xr1[rb * HH + t] = phi(Pr[m2]) + vbr;
            g_ln1[rb * HH + t] = phi(Pn[m2]) + vbn;
        }
    }
}

// ---------------- layer1 attention: warp per node, 4 edge-groups of 8 lanes ----------------
// lane = grp*8 + sub; lane handles dims [sub*8, sub*8+8) as two float4s.
// In-loop shfls use the GROUP mask only: trip counts differ between groups.
__global__ void attn1_kernel(const float* __restrict__ att,
                             const float* __restrict__ bias1) {
    int w = (blockIdx.x * blockDim.x + threadIdx.x) >> 5;
    int lane = threadIdx.x & 31;
    if (w >= NN) return;
    int grp = lane >> 3, sub = lane & 7;
    const unsigned gmask = 0xFFu << (grp * 8);

    const float4* xl4 = (const float4*)g_xl1;
    float4 xrA = ((const float4*)g_xr1)[w * 16 + sub * 2];
    float4 xrB = ((const float4*)g_xr1)[w * 16 + sub * 2 + 1];
    float4 atA = ((const float4*)att)[sub * 2];
    float4 atB = ((const float4*)att)[sub * 2 + 1];

    int beg = g_roff[w], end = g_roff[w + 1];

    float mx = -1e30f, den = 0.f;
    float4 aA = make_float4(0.f, 0.f, 0.f, 0.f);
    float4 aB = make_float4(0.f, 0.f, 0.f, 0.f);

    for (int e = beg + grp; e < end; e += 4) {
        int s = g_csrc[e];
        float4 vA = xl4[s * 16 + sub * 2];
        float4 vB = xl4[s * 16 + sub * 2 + 1];
        float p = lrelu(vA.x + xrA.x) * atA.x + lrelu(vA.y + xrA.y) * atA.y
                + lrelu(vA.z + xrA.z) * atA.z + lrelu(vA.w + xrA.w) * atA.w
                + lrelu(vB.x + xrB.x) * atB.x + lrelu(vB.y + xrB.y) * atB.y
                + lrelu(vB.z + xrB.z) * atB.z + lrelu(vB.w + xrB.w) * atB.w;
        p += __shfl_xor_sync(gmask, p, 1);
        p += __shfl_xor_sync(gmask, p, 2);
        p += __shfl_xor_sync(gmask, p, 4);
        float nmx = fmaxf(mx, p);
        float sc = __expf(mx - nmx);
        float ww = __expf(p - nmx);
        den = fmaf(den, sc, ww);
        aA.x = fmaf(aA.x, sc, ww * vA.x); aA.y = fmaf(aA.y, sc, ww * vA.y);
        aA.z = fmaf(aA.z, sc, ww * vA.z); aA.w = fmaf(aA.w, sc, ww * vA.w);
        aB.x = fmaf(aB.x, sc, ww * vB.x); aB.y = fmaf(aB.y, sc, ww * vB.y);
        aB.z = fmaf(aB.z, sc, ww * vB.z); aB.w = fmaf(aB.w, sc, ww * vB.w);
        mx = nmx;
    }

    // merge the 4 group states (warp reconverged here; full mask is safe)
#pragma unroll
    for (int msk = 8; msk <= 16; msk <<= 1) {
        float omx = __shfl_xor_sync(0xffffffffu, mx, msk);
        float nmx = fmaxf(mx, omx);
        float sc = __expf(mx - nmx);
        den *= sc;
        aA.x *= sc; aA.y *= sc; aA.z *= sc; aA.w *= sc;
        aB.x *= sc; aB.y *= sc; aB.z *= sc; aB.w *= sc;
        den += __shfl_xor_sync(0xffffffffu, den, msk);
        aA.x += __shfl_xor_sync(0xffffffffu, aA.x, msk);
        aA.y += __shfl_xor_sync(0xffffffffu, aA.y, msk);
        aA.z += __shfl_xor_sync(0xffffffffu, aA.z, msk);
        aA.w += __shfl_xor_sync(0xffffffffu, aA.w, msk);
        aB.x += __shfl_xor_sync(0xffffffffu, aB.x, msk);
        aB.y += __shfl_xor_sync(0xffffffffu, aB.y, msk);
        aB.z += __shfl_xor_sync(0xffffffffu, aB.z, msk);
        aB.w += __shfl_xor_sync(0xffffffffu, aB.w, msk);
        mx = nmx;
    }

    if (grp == 0) {
        float inv = 1.f / den;
        float4 lnA = ((const float4*)g_ln1)[w * 16 + sub * 2];
        float4 lnB = ((const float4*)g_ln1)[w * 16 + sub * 2 + 1];
        float4 bA = ((const float4*)bias1)[sub * 2];
        float4 bB = ((const float4*)bias1)[sub * 2 + 1];
        float4 hA, hB;
        hA.x = fmaxf(fmaf(aA.x, inv, bA.x + lnA.x), 0.f);
        hA.y = fmaxf(fmaf(aA.y, inv, bA.y + lnA.y), 0.f);
        hA.z = fmaxf(fmaf(aA.z, inv, bA.z + lnA.z), 0.f);
        hA.w = fmaxf(fmaf(aA.w, inv, bA.w + lnA.w), 0.f);
        hB.x = fmaxf(fmaf(aB.x, inv, bB.x + lnB.x), 0.f);
        hB.y = fmaxf(fmaf(aB.y, inv, bB.y + lnB.y), 0.f);
        hB.z = fmaxf(fmaf(aB.z, inv, bB.z + lnB.z), 0.f);
        hB.w = fmaxf(fmaf(aB.w, inv, bB.w + lnB.w), 0.f);
        ((float4*)g_h)[w * 16 + sub * 2] = hA;
        ((float4*)g_h)[w * 16 + sub * 2 + 1] = hB;
    }
}

// ---------------- layer2 node GEMMs ----------------
__global__ void __launch_bounds__(64) gemm2_kernel(
    const float* __restrict__ Wl, const float* __restrict__ bl,
    const float* __restrict__ Wr, const float* __restrict__ br,
    const float* __restrict__ Wn, const float* __restrict__ bn) {
    __shared__ float4 hs[16 * 16];
    const int t = threadIdx.x;
    const int row0 = blockIdx.x * 16;
    const float4* h4 = (const float4*)(g_h + row0 * HH);
#pragma unroll
    for (int i = 0; i < 4; i++) hs[i * 64 + t] = h4[i * 64 + t];
    __syncthreads();

    const bool act = (t < CC);
    float al[16], ar[16], an[16];
#pragma unroll
    for (int m = 0; m < 16; m++) { al[m] = 0.f; ar[m] = 0.f; an[m] = 0.f; }

    for (int k4 = 0; k4 < 16; k4++) {
        int k = 4 * k4;
        float wl0 = act ? __ldg(&Wl[(k + 0) * CC + t]) : 0.f;
        float wl1 = act ? __ldg(&Wl[(k + 1) * CC + t]) : 0.f;
        float wl2 = act ? __ldg(&Wl[(k + 2) * CC + t]) : 0.f;
        float wl3 = act ? __ldg(&Wl[(k + 3) * CC + t]) : 0.f;
        float wr0 = act ? __ldg(&Wr[(k + 0) * CC + t]) : 0.f;
        float wr1 = act ? __ldg(&Wr[(k + 1) * CC + t]) : 0.f;
        float wr2 = act ? __ldg(&Wr[(k + 2) * CC + t]) : 0.f;
        float wr3 = act ? __ldg(&Wr[(k + 3) * CC + t]) : 0.f;
        float wn0 = act ? __ldg(&Wn[(k + 0) * CC + t]) : 0.f;
        float wn1 = act ? __ldg(&Wn[(k + 1) * CC + t]) : 0.f;
        float wn2 = act ? __ldg(&Wn[(k + 2) * CC + t]) : 0.f;
        float wn3 = act ? __ldg(&Wn[(k + 3) * CC + t]) : 0.f;
#pragma unroll
        for (int m = 0; m < 16; m++) {
            float4 xv = hs[m * 16 + k4];
            al[m] = fmaf(xv.x, wl0, al[m]);
            al[m] = fmaf(xv.y, wl1, al[m]);
            al[m] = fmaf(xv.z, wl2, al[m]);
            al[m] = fmaf(xv.w, wl3, al[m]);
            ar[m] = fmaf(xv.x, wr0, ar[m]);
            ar[m] = fmaf(xv.y, wr1, ar[m]);
            ar[m] = fmaf(xv.z, wr2, ar[m]);
            ar[m] = fmaf(xv.w, wr3, ar[m]);
            an[m] = fmaf(xv.x, wn0, an[m]);
            an[m] = fmaf(xv.y, wn1, an[m]);
            an[m] = fmaf(xv.z, wn2, an[m]);
            an[m] = fmaf(xv.w, wn3, an[m]);
        }
    }
    if (act) {
        float vbl = __ldg(&bl[t]), vbr = __ldg(&br[t]), vbn = __ldg(&bn[t]);
#pragma unroll
        for (int m = 0; m < 16; m++) {
            int o = (row0 + m) * CC + t;
            g_xl2[o] = al[m] + vbl;
            g_xr2[o] = ar[m] + vbr;
            g_ln2[o] = an[m] + vbn;
        }
    }
}

// ---------------- layer2 attention + log_softmax: warp per node, 2 groups of 16 ----------------
// lane = grp*16 + sub; lanes with sub<10 handle dims [sub*4, sub*4+4).
__global__ void attn2_kernel(const float* __restrict__ att,
                             const float* __restrict__ bias2,
                             float* __restrict__ out) {
    int w = (blockIdx.x * blockDim.x + threadIdx.x) >> 5;
    int lane = threadIdx.x & 31;
    if (w >= NN) return;
    int grp = lane >> 4, sub = lane & 15;
    const bool act = (sub < 10);
    const unsigned gmask = 0xFFFFu << (grp * 16);

    const float4* xl4 = (const float4*)g_xl2;
    float4 xr = make_float4(0.f, 0.f, 0.f, 0.f);
    float4 at = make_float4(0.f, 0.f, 0.f, 0.f);
    if (act) {
        xr = ((const float4*)g_xr2)[w * 10 + sub];
        at = ((const float4*)att)[sub];
    }

    int beg = g_roff[w], end = g_roff[w + 1];

    float mx = -1e30f, den = 0.f;
    float4 ac = make_float4(0.f, 0.f, 0.f, 0.f);

    for (int e = beg + grp; e < end; e += 2) {
        int s = g_csrc[e];
        float4 v = make_float4(0.f, 0.f, 0.f, 0.f);
        if (act) v = xl4[s * 10 + sub];
        float p = lrelu(v.x + xr.x) * at.x + lrelu(v.y + xr.y) * at.y
                + lrelu(v.z + xr.z) * at.z + lrelu(v.w + xr.w) * at.w;
        p += __shfl_xor_sync(gmask, p, 1);
        p += __shfl_xor_sync(gmask, p, 2);
        p += __shfl_xor_sync(gmask, p, 4);
        p += __shfl_xor_sync(gmask, p, 8);
        float nmx = fmaxf(mx, p);
        float sc = __expf(mx - nmx);
        float ww = __expf(p - nmx);
        den = fmaf(den, sc, ww);
        ac.x = fmaf(ac.x, sc, ww * v.x); ac.y = fmaf(ac.y, sc, ww * v.y);
        ac.z = fmaf(ac.z, sc, ww * v.z); ac.w = fmaf(ac.w, sc, ww * v.w);
        mx = nmx;
    }

    // merge the 2 group states (warp reconverged; full mask safe)
    {
        float omx = __shfl_xor_sync(0xffffffffu, mx, 16);
        float nmx = fmaxf(mx, omx);
        float sc = __expf(mx - nmx);
        den *= sc;
        ac.x *= sc; ac.y *= sc; ac.z *= sc; ac.w *= sc;
        den += __shfl_xor_sync(0xffffffffu, den, 16);
        ac.x += __shfl_xor_sync(0xffffffffu, ac.x, 16);
        ac.y += __shfl_xor_sync(0xffffffffu, ac.y, 16);
        ac.z += __shfl_xor_sync(0xffffffffu, ac.z, 16);
        ac.w += __shfl_xor_sync(0xffffffffu, ac.w, 16);
        mx = nmx;
    }

    float inv = 1.f / den;
    float4 o4 = make_float4(-1e30f, -1e30f, -1e30f, -1e30f);
    if (act) {
        float4 ln = ((const float4*)g_ln2)[w * 10 + sub];
        float4 b4 = ((const float4*)bias2)[sub];
        o4.x = fmaf(ac.x, inv, b4.x + ln.x);
        o4.y = fmaf(ac.y, inv, b4.y + ln.y);
        o4.z = fmaf(ac.z, inv, b4.z + ln.z);
        o4.w = fmaf(ac.w, inv, b4.w + ln.w);
    }
    // log_softmax over 40 dims (uniform control flow; full mask safe)
    float m2 = fmaxf(fmaxf(o4.x, o4.y), fmaxf(o4.z, o4.w));
#pragma unroll
    for (int o = 8; o > 0; o >>= 1) m2 = fmaxf(m2, __shfl_xor_sync(0xffffffffu, m2, o));
    float se = act ? (expf(o4.x - m2) + expf(o4.y - m2) + expf(o4.z - m2) + expf(o4.w - m2)) : 0.f;
#pragma unroll
    for (int o = 8; o > 0; o >>= 1) se += __shfl_xor_sync(0xffffffffu, se, o);
    float ls = m2 + logf(se);
    if (act && grp == 0) {
        float4 r;
        r.x = o4.x - ls; r.y = o4.y - ls; r.z = o4.z - ls; r.w = o4.w - ls;
        ((float4*)out)[w * 10 + sub] = r;
    }
}

// ---------------- launch ----------------
extern "C" void kernel_launch(void* const* d_in, const int* in_sizes, int n_in,
                              void* d_out, int out_size) {
    const float* x     = (const float*)d_in[0];
    const void*  ei    = d_in[1];
    const float* W1l   = (const float*)d_in[2];
    const float* b1l   = (const float*)d_in[3];
    const float* W1r   = (const float*)d_in[4];
    const float* b1r   = (const float*)d_in[5];
    const float* att1  = (const float*)d_in[6];
    const float* bias1 = (const float*)d_in[7];
    const float* l1W   = (const float*)d_in[8];
    const float* l1b   = (const float*)d_in[9];
    const float* W2l   = (const float*)d_in[10];
    const float* b2l   = (const float*)d_in[11];
    const float* W2r   = (const float*)d_in[12];
    const float* b2r   = (const float*)d_in[13];
    const float* att2  = (const float*)d_in[14];
    const float* bias2 = (const float*)d_in[15];
    const float* l2W   = (const float*)d_in[16];
    const float* l2b   = (const float*)d_in[17];
    float* out = (float*)d_out;
    int do_pass = (out_size >= NN * CC + 2 * EE) ? 1 : 0;

    detect_kernel<<<1, 32>>>(ei);
    zero_cnt_kernel<<<NB, 256>>>();
    convert_count_kernel<<<(ET + 255) / 256, 256>>>(ei, out, do_pass);
    gemm1_kernel<<<(NN + 31) / 32, 128>>>(x, W1l, b1l, W1r, b1r, l1W, l1b);  // index 3: profiled
    bsum_kernel<<<NB, 256>>>();
    bscan_kernel<<<1, 256>>>();
    offs_kernel<<<NB, 256>>>();
    scatter_kernel<<<(ET + 255) / 256, 256>>>();

    attn1_kernel<<<(NN * 32 + 255) / 256, 256>>>(att1, bias1);

    gemm2_kernel<<<NN / 16, 64>>>(W2l, b2l, W2r, b2r, l2W, l2b);
    attn2_kernel<<<(NN * 32 + 255) / 256, 256>>>(att2, bias2, out);
}

// round 6
// speedup vs baseline: 1.0411x; 1.0411x over previous
#include <cuda_runtime.h>
#include <math.h>

#define NN 50000
#define EE 800000
#define ET (EE + NN)
#define FIN 256
#define HH 64
#define CC 40
#define NEG_SLOPE 0.2f
#define NB ((NN + 255) / 256)

typedef unsigned long long u64;

// ---------------- scratch (__device__ globals; no allocation) ----------------
static __device__ int g_is64;
static __device__ int g_src[ET];
static __device__ int g_dst[ET];
static __device__ int g_cnt[NN];
static __device__ int g_roff[NN + 1];
static __device__ int g_cursor[NN];
static __device__ int g_csrc[ET];
static __device__ int g_bsum[NB];
static __device__ int g_bpre[NB];

static __device__ float g_xl1[NN * HH];
static __device__ float g_xr1[NN * HH];
static __device__ float g_ln1[NN * HH];
static __device__ float g_h[NN * HH];

static __device__ float g_xl2[NN * CC];
static __device__ float g_xr2[NN * CC];
static __device__ float g_ln2[NN * CC];

// ---------------- f32x2 packed-FMA helpers (sm_103a) ----------------
__device__ __forceinline__ void fma2(u64& acc, u64 a, u64 b) {
    asm("fma.rn.f32x2 %0, %1, %2, %0;" : "+l"(acc) : "l"(a), "l"(b));
}
__device__ __forceinline__ float plo(u64 v) { return __uint_as_float((unsigned)v); }
__device__ __forceinline__ float phi(u64 v) { return __uint_as_float((unsigned)(v >> 32)); }

__device__ __forceinline__ float lrelu(float v) { return fmaxf(v, NEG_SLOPE * v); }

// ---------------- edge index dtype detect ----------------
__global__ void detect_kernel(const void* edge) {
    const int* p = (const int*)edge;
    int ok64 = 1;
    for (int i = threadIdx.x * 2 + 1; i < 4096; i += 64)
        if (p[i] != 0) ok64 = 0;
    unsigned b = __ballot_sync(0xffffffffu, ok64);
    if (threadIdx.x == 0) g_is64 = (b == 0xffffffffu) ? 1 : 0;
}

__global__ void zero_cnt_kernel() {
    int i = blockIdx.x * blockDim.x + threadIdx.x;
    if (i < NN) g_cnt[i] = 0;
}

// convert edge list (+self loops), histogram dst, emit edge_index passthrough
__global__ void convert_count_kernel(const void* edge, float* __restrict__ out, int do_pass) {
    int t = blockIdx.x * blockDim.x + threadIdx.x;
    if (t >= ET) return;
    int s, d;
    if (t >= EE) {
        s = t - EE; d = t - EE;
    } else if (g_is64) {
        const long long* p = (const long long*)edge;
        s = (int)p[t]; d = (int)p[EE + t];
    } else {
        const int* p = (const int*)edge;
        s = p[t]; d = p[EE + t];
    }
    g_src[t] = s;
    g_dst[t] = d;
    atomicAdd(&g_cnt[d], 1);
    if (do_pass && t < EE) {
        out[NN * CC + t] = (float)s;
        out[NN * CC + EE + t] = (float)d;
    }
}

// ---------------- 3-stage parallel scan over g_cnt ----------------
__global__ void bsum_kernel() {
    __shared__ int ws[8];
    int i = blockIdx.x * 256 + threadIdx.x;
    int lane = threadIdx.x & 31, w = threadIdx.x >> 5;
    int v = (i < NN) ? g_cnt[i] : 0;
#pragma unroll
    for (int o = 16; o > 0; o >>= 1) v += __shfl_xor_sync(0xffffffffu, v, o);
    if (lane == 0) ws[w] = v;
    __syncthreads();
    if (threadIdx.x == 0) {
        int s = 0;
#pragma unroll
        for (int k = 0; k < 8; k++) s += ws[k];
        g_bsum[blockIdx.x] = s;
    }
}

__global__ void bscan_kernel() {  // 1 block, 256 threads; NB <= 256
    __shared__ int ws[8];
    int t = threadIdx.x;
    int lane = t & 31, w = t >> 5;
    int v = (t < NB) ? g_bsum[t] : 0;
    int x = v;
#pragma unroll
    for (int dlt = 1; dlt < 32; dlt <<= 1) {
        int y = __shfl_up_sync(0xffffffffu, x, dlt);
        if (lane >= dlt) x += y;
    }
    if (lane == 31) ws[w] = x;
    __syncthreads();
    if (w == 0 && lane < 8) {
        int s = ws[lane];
#pragma unroll
        for (int dlt = 1; dlt < 8; dlt <<= 1) {
            int y = __shfl_up_sync(0xffu, s, dlt);
            if (lane >= dlt) s += y;
        }
        ws[lane] = s;
    }
    __syncthreads();
    int prefix = (w > 0) ? ws[w - 1] : 0;
    if (t < NB) g_bpre[t] = prefix + x - v;
}

__global__ void offs_kernel() {
    __shared__ int ws[8];
    int i = blockIdx.x * 256 + threadIdx.x;
    int lane = threadIdx.x & 31, w = threadIdx.x >> 5;
    int v = (i < NN) ? g_cnt[i] : 0;
    int x = v;
#pragma unroll
    for (int dlt = 1; dlt < 32; dlt <<= 1) {
        int y = __shfl_up_sync(0xffffffffu, x, dlt);
        if (lane >= dlt) x += y;
    }
    if (lane == 31) ws[w] = x;
    __syncthreads();
    if (w == 0 && lane < 8) {
        int s = ws[lane];
#pragma unroll
        for (int dlt = 1; dlt < 8; dlt <<= 1) {
            int y = __shfl_up_sync(0xffu, s, dlt);
            if (lane >= dlt) s += y;
        }
        ws[lane] = s;
    }
    __syncthreads();
    int prefix = (w > 0) ? ws[w - 1] : 0;
    int excl = g_bpre[blockIdx.x] + prefix + x - v;
    if (i < NN) {
        g_cursor[i] = excl;
        g_roff[i + 1] = excl + v;
    }
    if (i == 0) g_roff[0] = 0;
}

__global__ void scatter_kernel() {
    int t = blockIdx.x * blockDim.x + threadIdx.x;
    if (t >= ET) return;
    int d = g_dst[t];
    int pos = atomicAdd(&g_cursor[d], 1);
    g_csrc[pos] = g_src[t];
}

// ---------------- layer1 node GEMMs: xl1/xr1/lin1 fused, f32x2, col-pair packing ----
// Block 128 = 4 warps, 32 rows (8 per warp). Lane l owns output cols (2l, 2l+1).
// SMEM holds x duplicated per element so the FFMA2 x-operand is a direct LDS;
// the weight operand (W[k][2l], W[k][2l+1]) is a contiguous LDG.64. Zero packing movs.
__global__ void __launch_bounds__(128) gemm1_kernel(
    const float* __restrict__ x,
    const float* __restrict__ Wl, const float* __restrict__ bl,
    const float* __restrict__ Wr, const float* __restrict__ br,
    const float* __restrict__ Wn, const float* __restrict__ bn) {
    __shared__ float2 xd[32][256];  // 64KB: xd[r][k] = (x[row0+r][k], x[row0+r][k])
    const int tid = threadIdx.x;
    const int w = tid >> 5, l = tid & 31;
    const int row0 = blockIdx.x * 32;

    // cooperative load + duplicate
    const float4* x4 = (const float4*)x;
    for (int i = tid; i < 32 * 64; i += 128) {
        int r = i >> 6, c4 = i & 63;
        int rr = row0 + r;
        float4 v = make_float4(0.f, 0.f, 0.f, 0.f);
        if (rr < NN) v = x4[rr * 64 + c4];
        float4* dst = (float4*)&xd[r][c4 * 4];
        dst[0] = make_float4(v.x, v.x, v.y, v.y);
        dst[1] = make_float4(v.z, v.z, v.w, v.w);
    }
    __syncthreads();

    const u64* Wl64 = (const u64*)Wl;
    const u64* Wr64 = (const u64*)Wr;
    const u64* Wn64 = (const u64*)Wn;

    u64 Al[8], Ar[8], An[8];
#pragma unroll
    for (int m = 0; m < 8; m++) { Al[m] = 0ull; Ar[m] = 0ull; An[m] = 0ull; }

#pragma unroll 2
    for (int k2 = 0; k2 < 128; k2++) {
        int k = 2 * k2;
        u64 wl0 = __ldg(&Wl64[(k + 0) * 32 + l]);
        u64 wl1 = __ldg(&Wl64[(k + 1) * 32 + l]);
        u64 wr0 = __ldg(&Wr64[(k + 0) * 32 + l]);
        u64 wr1 = __ldg(&Wr64[(k + 1) * 32 + l]);
        u64 wn0 = __ldg(&Wn64[(k + 0) * 32 + l]);
        u64 wn1 = __ldg(&Wn64[(k + 1) * 32 + l]);
#pragma unroll
        for (int m = 0; m < 8; m++) {
            longlong2 xx = *(const longlong2*)&xd[w * 8 + m][k];
            u64 x0 = (u64)xx.x, x1 = (u64)xx.y;
            fma2(Al[m], x0, wl0); fma2(Al[m], x1, wl1);
            fma2(Ar[m], x0, wr0); fma2(Ar[m], x1, wr1);
            fma2(An[m], x0, wn0); fma2(An[m], x1, wn1);
        }
    }

    float2 vbl = __ldg(&((const float2*)bl)[l]);
    float2 vbr = __ldg(&((const float2*)br)[l]);
    float2 vbn = __ldg(&((const float2*)bn)[l]);
#pragma unroll
    for (int m = 0; m < 8; m++) {
        int r = row0 + w * 8 + m;
        if (r < NN) {
            ((float2*)&g_xl1[r * HH])[l] = make_float2(plo(Al[m]) + vbl.x, phi(Al[m]) + vbl.y);
            ((float2*)&g_xr1[r * HH])[l] = make_float2(plo(Ar[m]) + vbr.x, phi(Ar[m]) + vbr.y);
            ((float2*)&g_ln1[r * HH])[l] = make_float2(plo(An[m]) + vbn.x, phi(An[m]) + vbn.y);
        }
    }
}

// ---------------- layer1 attention: warp per node, 4 edge-groups of 8 lanes ----------------
__global__ void attn1_kernel(const float* __restrict__ att,
                             const float* __restrict__ bias1) {
    int w = (blockIdx.x * blockDim.x + threadIdx.x) >> 5;
    int lane = threadIdx.x & 31;
    if (w >= NN) return;
    int grp = lane >> 3, sub = lane & 7;
    const unsigned gmask = 0xFFu << (grp * 8);

    const float4* xl4 = (const float4*)g_xl1;
    float4 xrA = ((const float4*)g_xr1)[w * 16 + sub * 2];
    float4 xrB = ((const float4*)g_xr1)[w * 16 + sub * 2 + 1];
    float4 atA = ((const float4*)att)[sub * 2];
    float4 atB = ((const float4*)att)[sub * 2 + 1];

    int beg = g_roff[w], end = g_roff[w + 1];

    float mx = -1e30f, den = 0.f;
    float4 aA = make_float4(0.f, 0.f, 0.f, 0.f);
    float4 aB = make_float4(0.f, 0.f, 0.f, 0.f);

    for (int e = beg + grp; e < end; e += 4) {
        int s = g_csrc[e];
        float4 vA = xl4[s * 16 + sub * 2];
        float4 vB = xl4[s * 16 + sub * 2 + 1];
        float p = lrelu(vA.x + xrA.x) * atA.x + lrelu(vA.y + xrA.y) * atA.y
                + lrelu(vA.z + xrA.z) * atA.z + lrelu(vA.w + xrA.w) * atA.w
                + lrelu(vB.x + xrB.x) * atB.x + lrelu(vB.y + xrB.y) * atB.y
                + lrelu(vB.z + xrB.z) * atB.z + lrelu(vB.w + xrB.w) * atB.w;
        p += __shfl_xor_sync(gmask, p, 1);
        p += __shfl_xor_sync(gmask, p, 2);
        p += __shfl_xor_sync(gmask, p, 4);
        float nmx = fmaxf(mx, p);
        float sc = __expf(mx - nmx);
        float ww = __expf(p - nmx);
        den = fmaf(den, sc, ww);
        aA.x = fmaf(aA.x, sc, ww * vA.x); aA.y = fmaf(aA.y, sc, ww * vA.y);
        aA.z = fmaf(aA.z, sc, ww * vA.z); aA.w = fmaf(aA.w, sc, ww * vA.w);
        aB.x = fmaf(aB.x, sc, ww * vB.x); aB.y = fmaf(aB.y, sc, ww * vB.y);
        aB.z = fmaf(aB.z, sc, ww * vB.z); aB.w = fmaf(aB.w, sc, ww * vB.w);
        mx = nmx;
    }

    // merge the 4 group states (warp reconverged here; full mask is safe)
#pragma unroll
    for (int msk = 8; msk <= 16; msk <<= 1) {
        float omx = __shfl_xor_sync(0xffffffffu, mx, msk);
        float nmx = fmaxf(mx, omx);
        float sc = __expf(mx - nmx);
        den *= sc;
        aA.x *= sc; aA.y *= sc; aA.z *= sc; aA.w *= sc;
        aB.x *= sc; aB.y *= sc; aB.z *= sc; aB.w *= sc;
        den += __shfl_xor_sync(0xffffffffu, den, msk);
        aA.x += __shfl_xor_sync(0xffffffffu, aA.x, msk);
        aA.y += __shfl_xor_sync(0xffffffffu, aA.y, msk);
        aA.z += __shfl_xor_sync(0xffffffffu, aA.z, msk);
        aA.w += __shfl_xor_sync(0xffffffffu, aA.w, msk);
        aB.x += __shfl_xor_sync(0xffffffffu, aB.x, msk);
        aB.y += __shfl_xor_sync(0xffffffffu, aB.y, msk);
        aB.z += __shfl_xor_sync(0xffffffffu, aB.z, msk);
        aB.w += __shfl_xor_sync(0xffffffffu, aB.w, msk);
        mx = nmx;
    }

    if (grp == 0) {
        float inv = 1.f / den;
        float4 lnA = ((const float4*)g_ln1)[w * 16 + sub * 2];
        float4 lnB = ((const float4*)g_ln1)[w * 16 + sub * 2 + 1];
        float4 bA = ((const float4*)bias1)[sub * 2];
        float4 bB = ((const float4*)bias1)[sub * 2 + 1];
        float4 hA, hB;
        hA.x = fmaxf(fmaf(aA.x, inv, bA.x + lnA.x), 0.f);
        hA.y = fmaxf(fmaf(aA.y, inv, bA.y + lnA.y), 0.f);
        hA.z = fmaxf(fmaf(aA.z, inv, bA.z + lnA.z), 0.f);
        hA.w = fmaxf(fmaf(aA.w, inv, bA.w + lnA.w), 0.f);
        hB.x = fmaxf(fmaf(aB.x, inv, bB.x + lnB.x), 0.f);
        hB.y = fmaxf(fmaf(aB.y, inv, bB.y + lnB.y), 0.f);
        hB.z = fmaxf(fmaf(aB.z, inv, bB.z + lnB.z), 0.f);
        hB.w = fmaxf(fmaf(aB.w, inv, bB.w + lnB.w), 0.f);
        ((float4*)g_h)[w * 16 + sub * 2] = hA;
        ((float4*)g_h)[w * 16 + sub * 2 + 1] = hB;
    }
}

// ---------------- layer2 node GEMMs: 120 active threads, 3 row-groups x 40 cols ----
__global__ void __launch_bounds__(128) gemm2_kernel(
    const float* __restrict__ Wl, const float* __restrict__ bl,
    const float* __restrict__ Wr, const float* __restrict__ br,
    const float* __restrict__ Wn, const float* __restrict__ bn) {
    __shared__ float hs[24][65];  // padded to avoid 3-group bank conflicts
    const int t = threadIdx.x;
    const int row0 = blockIdx.x * 24;

    // load h tile: 24 rows x 64 cols
    for (int i = t; i < 24 * 64; i += 128) {
        int r = i >> 6, c = i & 63;
        int rr = row0 + r;
        hs[r][c] = (rr < NN) ? g_h[rr * HH + c] : 0.f;
    }
    __syncthreads();

    if (t >= 120) return;
    int g = t / 40;           // row group 0..2
    int c = t - g * 40;       // output col 0..39

    float al[8], ar[8], an[8];
#pragma unroll
    for (int m = 0; m < 8; m++) { al[m] = 0.f; ar[m] = 0.f; an[m] = 0.f; }

    for (int k = 0; k < HH; k++) {
        float wl = __ldg(&Wl[k * CC + c]);
        float wr = __ldg(&Wr[k * CC + c]);
        float wn = __ldg(&Wn[k * CC + c]);
#pragma unroll
        for (int m = 0; m < 8; m++) {
            float hv = hs[g * 8 + m][k];
            al[m] = fmaf(hv, wl, al[m]);
            ar[m] = fmaf(hv, wr, ar[m]);
            an[m] = fmaf(hv, wn, an[m]);
        }
    }
    float vbl = __ldg(&bl[c]), vbr = __ldg(&br[c]), vbn = __ldg(&bn[c]);
#pragma unroll
    for (int m = 0; m < 8; m++) {
        int r = row0 + g * 8 + m;
        if (r < NN) {
            int o = r * CC + c;
            g_xl2[o] = al[m] + vbl;
            g_xr2[o] = ar[m] + vbr;
            g_ln2[o] = an[m] + vbn;
        }
    }
}

// ---------------- layer2 attention + log_softmax: warp per node, 2 groups of 16 ----------------
__global__ void attn2_kernel(const float* __restrict__ att,
                             const float* __restrict__ bias2,
                             float* __restrict__ out) {
    int w = (blockIdx.x * blockDim.x + threadIdx.x) >> 5;
    int lane = threadIdx.x & 31;
    if (w >= NN) return;
    int grp = lane >> 4, sub = lane & 15;
    const bool act = (sub < 10);
    const unsigned gmask = 0xFFFFu << (grp * 16);

    const float4* xl4 = (const float4*)g_xl2;
    float4 xr = make_float4(0.f, 0.f, 0.f, 0.f);
    float4 at = make_float4(0.f, 0.f, 0.f, 0.f);
    if (act) {
        xr = ((const float4*)g_xr2)[w * 10 + sub];
        at = ((const float4*)att)[sub];
    }

    int beg = g_roff[w], end = g_roff[w + 1];

    float mx = -1e30f, den = 0.f;
    float4 ac = make_float4(0.f, 0.f, 0.f, 0.f);

    for (int e = beg + grp; e < end; e += 2) {
        int s = g_csrc[e];
        float4 v = make_float4(0.f, 0.f, 0.f, 0.f);
        if (act) v = xl4[s * 10 + sub];
        float p = lrelu(v.x + xr.x) * at.x + lrelu(v.y + xr.y) * at.y
                + lrelu(v.z + xr.z) * at.z + lrelu(v.w + xr.w) * at.w;
        p += __shfl_xor_sync(gmask, p, 1);
        p += __shfl_xor_sync(gmask, p, 2);
        p += __shfl_xor_sync(gmask, p, 4);
        p += __shfl_xor_sync(gmask, p, 8);
        float nmx = fmaxf(mx, p);
        float sc = __expf(mx - nmx);
        float ww = __expf(p - nmx);
        den = fmaf(den, sc, ww);
        ac.x = fmaf(ac.x, sc, ww * v.x); ac.y = fmaf(ac.y, sc, ww * v.y);
        ac.z = fmaf(ac.z, sc, ww * v.z); ac.w = fmaf(ac.w, sc, ww * v.w);
        mx = nmx;
    }

    // merge the 2 group states (warp reconverged; full mask safe)
    {
        float omx = __shfl_xor_sync(0xffffffffu, mx, 16);
        float nmx = fmaxf(mx, omx);
        float sc = __expf(mx - nmx);
        den *= sc;
        ac.x *= sc; ac.y *= sc; ac.z *= sc; ac.w *= sc;
        den += __shfl_xor_sync(0xffffffffu, den, 16);
        ac.x += __shfl_xor_sync(0xffffffffu, ac.x, 16);
        ac.y += __shfl_xor_sync(0xffffffffu, ac.y, 16);
        ac.z += __shfl_xor_sync(0xffffffffu, ac.z, 16);
        ac.w += __shfl_xor_sync(0xffffffffu, ac.w, 16);
        mx = nmx;
    }

    float inv = 1.f / den;
    float4 o4 = make_float4(-1e30f, -1e30f, -1e30f, -1e30f);
    if (act) {
        float4 ln = ((const float4*)g_ln2)[w * 10 + sub];
        float4 b4 = ((const float4*)bias2)[sub];
        o4.x = fmaf(ac.x, inv, b4.x + ln.x);
        o4.y = fmaf(ac.y, inv, b4.y + ln.y);
        o4.z = fmaf(ac.z, inv, b4.z + ln.z);
        o4.w = fmaf(ac.w, inv, b4.w + ln.w);
    }
    float m2 = fmaxf(fmaxf(o4.x, o4.y), fmaxf(o4.z, o4.w));
#pragma unroll
    for (int o = 8; o > 0; o >>= 1) m2 = fmaxf(m2, __shfl_xor_sync(0xffffffffu, m2, o));
    float se = act ? (expf(o4.x - m2) + expf(o4.y - m2) + expf(o4.z - m2) + expf(o4.w - m2)) : 0.f;
#pragma unroll
    for (int o = 8; o > 0; o >>= 1) se += __shfl_xor_sync(0xffffffffu, se, o);
    float ls = m2 + logf(se);
    if (act && grp == 0) {
        float4 r;
        r.x = o4.x - ls; r.y = o4.y - ls; r.z = o4.z - ls; r.w = o4.w - ls;
        ((float4*)out)[w * 10 + sub] = r;
    }
}

// ---------------- launch ----------------
extern "C" void kernel_launch(void* const* d_in, const int* in_sizes, int n_in,
                              void* d_out, int out_size) {
    const float* x     = (const float*)d_in[0];
    const void*  ei    = d_in[1];
    const float* W1l   = (const float*)d_in[2];
    const float* b1l   = (const float*)d_in[3];
    const float* W1r   = (const float*)d_in[4];
    const float* b1r   = (const float*)d_in[5];
    const float* att1  = (const float*)d_in[6];
    const float* bias1 = (const float*)d_in[7];
    const float* l1W   = (const float*)d_in[8];
    const float* l1b   = (const float*)d_in[9];
    const float* W2l   = (const float*)d_in[10];
    const float* b2l   = (const float*)d_in[11];
    const float* W2r   = (const float*)d_in[12];
    const float* b2r   = (const float*)d_in[13];
    const float* att2  = (const float*)d_in[14];
    const float* bias2 = (const float*)d_in[15];
    const float* l2W   = (const float*)d_in[16];
    const float* l2b   = (const float*)d_in[17];
    float* out = (float*)d_out;
    int do_pass = (out_size >= NN * CC + 2 * EE) ? 1 : 0;

    detect_kernel<<<1, 32>>>(ei);
    zero_cnt_kernel<<<NB, 256>>>();
    convert_count_kernel<<<(ET + 255) / 256, 256>>>(ei, out, do_pass);
    gemm1_kernel<<<(NN + 31) / 32, 128>>>(x, W1l, b1l, W1r, b1r, l1W, l1b);  // index 3: profiled
    bsum_kernel<<<NB, 256>>>();
    bscan_kernel<<<1, 256>>>();
    offs_kernel<<<NB, 256>>>();
    scatter_kernel<<<(ET + 255) / 256, 256>>>();

    attn1_kernel<<<(NN * 32 + 255) / 256, 256>>>(att1, bias1);

    gemm2_kernel<<<(NN + 23) / 24, 128>>>(W2l, b2l, W2r, b2r, l2W, l2b);
    attn2_kernel<<<(NN * 32 + 255) / 256, 256>>>(att2, bias2, out);
}